// round 15
// baseline (speedup 1.0000x reference)
#include <cuda_runtime.h>
#include <cuda_fp16.h>
#include <cstdint>

typedef unsigned long long ull;

// ---------------- scratch ----------------------------------------------------
__device__ float g_kt1p[32 * 1024];              // FWHT2D(filter1)/32768, pair-interleaved
__device__ float g_kt2p[64 * 256];               // FWHT2D(filter2)/4096, pair-interleaved
__device__ __half g_a[2048 * 4096];              // activations (fp16)
__device__ __half g_w[512 * 4096];               // fc1 weights (fp16)
__device__ float g_h[2 * 2048 * 512];            // fc1 partials (2 K-splits)

// ---------------- PTX helpers (baseline ISA only) -----------------------------
__device__ __forceinline__ uint32_t smem_u32(const void* p) {
    uint32_t a;
    asm("{ .reg .u64 t; cvta.to.shared.u64 t, %1; cvt.u32.u64 %0, t; }" : "=r"(a) : "l"(p));
    return a;
}
__device__ __forceinline__ void cpasync16(uint32_t dst, const void* src) {
    asm volatile("cp.async.cg.shared.global [%0], [%1], 16;" :: "r"(dst), "l"(src));
}
__device__ __forceinline__ void cp_commit() {
    asm volatile("cp.async.commit_group;" ::: "memory");
}
__device__ __forceinline__ void ldsm_x4(uint32_t addr, uint32_t* r) {
    asm volatile("ldmatrix.sync.aligned.m8n8.x4.shared.b16 {%0,%1,%2,%3}, [%4];"
                 : "=r"(r[0]), "=r"(r[1]), "=r"(r[2]), "=r"(r[3]) : "r"(addr));
}
__device__ __forceinline__ void mma_f16(float* d, const uint32_t* a, const uint32_t* b) {
    asm volatile(
        "mma.sync.aligned.m16n8k16.row.col.f32.f16.f16.f32 "
        "{%0,%1,%2,%3}, {%4,%5,%6,%7}, {%8,%9}, {%0,%1,%2,%3};"
        : "+f"(d[0]), "+f"(d[1]), "+f"(d[2]), "+f"(d[3])
        : "r"(a[0]), "r"(a[1]), "r"(a[2]), "r"(a[3]), "r"(b[0]), "r"(b[1]));
}
__device__ __forceinline__ ull pack2(float lo, float hi) {
    ull r; asm("mov.b64 %0, {%1,%2};" : "=l"(r) : "f"(lo), "f"(hi)); return r;
}
__device__ __forceinline__ void unpack2(ull v, float& lo, float& hi) {
    asm("mov.b64 {%0,%1}, %2;" : "=f"(lo), "=f"(hi) : "l"(v));
}
__device__ __forceinline__ ull fma2(ull a, ull b, ull c) {
    ull r; asm("fma.rn.f32x2 %0, %1, %2, %3;" : "=l"(r) : "l"(a), "l"(b), "l"(c)); return r;
}
#define ONE2 0x3F8000003F800000ULL
#define NEG2 0xBF800000BF800000ULL
#define ZERO2 0x0000000000000000ULL

// swizzled byte offset within a 256B row (K-chunk 128 fp16): ck in 16B units 0..15
__device__ __forceinline__ uint32_t swz256(int row, int ck) {
    return row * 256 + (ck >> 3) * 128 + (((ck & 7) ^ (row & 7)) * 16);
}

// ---------------- K0: filter transform (pair-interleaved) + fc1 w -> fp16 -----
__global__ void k0_prep(const float* __restrict__ f1, const float* __restrict__ f2,
                        const float* __restrict__ W) {
    int gid = blockIdx.x * 256 + threadIdx.x;
    {
        int i = gid * 4;
        float4 v = *(const float4*)(W + i);
        *(__half2*)(g_w + i) = __floats2half2_rn(v.x, v.y);
        *(__half2*)(g_w + i + 2) = __floats2half2_rn(v.z, v.w);
    }
    if (gid < 32 * 1024) {
        int f = gid >> 10, ij = gid & 1023, row = ij >> 5, col = ij & 31;
        float s = 0.f;
        for (int p = 0; p < 3; p++)
            for (int q = 0; q < 3; q++) {
                float v = f1[f * 9 + p * 3 + q];
                s += ((__popc(row & p) + __popc(col & q)) & 1) ? -v : v;
            }
        g_kt1p[(f * 16 + (row >> 1)) * 64 + col * 2 + (row & 1)] = s * (1.0f / 32768.0f);
    } else if (gid < 32 * 1024 + 64 * 256) {
        int k = gid - 32 * 1024;
        int f = k >> 8, ij = k & 255, row = ij >> 4, col = ij & 15;
        float s = 0.f;
        for (int p = 0; p < 3; p++)
            for (int q = 0; q < 3; q++) {
                float v = f2[f * 9 + p * 3 + q];
                s += ((__popc(row & p) + __popc(col & q)) & 1) ? -v : v;
            }
        g_kt2p[(f * 8 + (row >> 1)) * 32 + col * 2 + (row & 1)] = s * (1.0f / 4096.0f);
    }
}

// ---------------- K12: fused layer1 + layer2 (256 threads, one image) ---------
__global__ void __launch_bounds__(256) k12_conv(const float* __restrict__ x,
                                                const float* __restrict__ bias1,
                                                const float* __restrict__ bias2) {
    int b = blockIdx.x, tid = threadIdx.x;
    int w = tid >> 5, lane = tid & 31;
    __shared__ __align__(16) float W[8][32][36];   // 36864 B; reused as W2 in phase B
    __shared__ float P[8][16][16];                 // 8192 B
    __shared__ float S2[16][17];                   // 1088 B
    float (*S)[33] = (float(*)[33]) & W[0][0][0];

    // ===== phase A: layer 1 (identical to standalone k1) =====
    {   // channel sum
        const float* xb = x + (size_t)b * 3072;
        int base = tid * 4, r = base >> 5, c = base & 31;
        float4 v0 = *(const float4*)(xb + base);
        float4 v1 = *(const float4*)(xb + 1024 + base);
        float4 v2 = *(const float4*)(xb + 2048 + base);
        S[r][c + 0] = v0.x + v1.x + v2.x;
        S[r][c + 1] = v0.y + v1.y + v2.y;
        S[r][c + 2] = v0.z + v1.z + v2.z;
        S[r][c + 3] = v0.w + v1.w + v2.w;
    }
    __syncthreads();
    {
        float v0 = S[w * 4 + 0][lane], v1 = S[w * 4 + 1][lane];
        float v2 = S[w * 4 + 2][lane], v3 = S[w * 4 + 3][lane];
#pragma unroll
        for (int m = 1; m < 32; m <<= 1) {
            float o0 = __shfl_xor_sync(~0u, v0, m), o1 = __shfl_xor_sync(~0u, v1, m);
            float o2 = __shfl_xor_sync(~0u, v2, m), o3 = __shfl_xor_sync(~0u, v3, m);
            bool hi = (lane & m) != 0;
            v0 = hi ? o0 - v0 : o0 + v0; v1 = hi ? o1 - v1 : o1 + v1;
            v2 = hi ? o2 - v2 : o2 + v2; v3 = hi ? o3 - v3 : o3 + v3;
        }
        S[w * 4 + 0][lane] = v0; S[w * 4 + 1][lane] = v1;
        S[w * 4 + 2][lane] = v2; S[w * 4 + 3][lane] = v3;
    }
    __syncthreads();
    {
        float v0 = S[lane][w * 4 + 0], v1 = S[lane][w * 4 + 1];
        float v2 = S[lane][w * 4 + 2], v3 = S[lane][w * 4 + 3];
#pragma unroll
        for (int m = 1; m < 32; m <<= 1) {
            float o0 = __shfl_xor_sync(~0u, v0, m), o1 = __shfl_xor_sync(~0u, v1, m);
            float o2 = __shfl_xor_sync(~0u, v2, m), o3 = __shfl_xor_sync(~0u, v3, m);
            bool hi = (lane & m) != 0;
            v0 = hi ? o0 - v0 : o0 + v0; v1 = hi ? o1 - v1 : o1 + v1;
            v2 = hi ? o2 - v2 : o2 + v2; v3 = hi ? o3 - v3 : o3 + v3;
        }
        S[lane][w * 4 + 0] = v0; S[lane][w * 4 + 1] = v1;
        S[lane][w * 4 + 2] = v2; S[lane][w * 4 + 3] = v3;
    }
    __syncthreads();

    ull sp[16];
#pragma unroll
    for (int i = 0; i < 16; i++) sp[i] = pack2(S[2 * i][lane], S[2 * i + 1][lane]);
    __syncthreads();

    float acc[16];
#pragma unroll
    for (int k = 0; k < 16; k++) acc[k] = 0.f;
    float* Wp = &W[w][0][0];

#pragma unroll 1
    for (int ff = 0; ff < 4; ff++) {
        int f = w + ff * 8;
        const ull* kt = (const ull*)g_kt1p + (size_t)f * 512 + lane;
        ull tp[16];
#pragma unroll
        for (int i = 0; i < 16; i++) tp[i] = fma2(sp[i], __ldg(kt + i * 32), ZERO2);
#pragma unroll
        for (int mm = 1; mm < 16; mm <<= 1) {
#pragma unroll
            for (int i = 0; i < 16; i++)
                if (!(i & mm)) {
                    ull lo = tp[i], hi = tp[i | mm];
                    tp[i] = fma2(hi, ONE2, lo);
                    tp[i | mm] = fma2(hi, NEG2, lo);
                }
        }
        __syncwarp();
#pragma unroll
        for (int i = 0; i < 16; i++) {
            float a, c;
            unpack2(tp[i], a, c);
            Wp[(2 * i) * 36 + lane] = a + c;
            Wp[(2 * i + 1) * 36 + lane] = a - c;
        }
        __syncwarp();
        ull up[16];
#pragma unroll
        for (int j = 0; j < 8; j++) {
            float4 v = *(const float4*)(Wp + lane * 36 + 4 * j);
            up[2 * j] = pack2(v.x, v.y);
            up[2 * j + 1] = pack2(v.z, v.w);
        }
#pragma unroll
        for (int mm = 1; mm < 16; mm <<= 1) {
#pragma unroll
            for (int i = 0; i < 16; i++)
                if (!(i & mm)) {
                    ull lo = up[i], hi = up[i | mm];
                    up[i] = fma2(hi, ONE2, lo);
                    up[i | mm] = fma2(hi, NEG2, lo);
                }
        }
        float bf = __ldg(bias1 + f);
#pragma unroll
        for (int k = 0; k < 16; k++) {
            float A, B;
            unpack2(up[k], A, B);
            float t = A + fabsf(B);
            float o = __shfl_xor_sync(~0u, t, 1);
            float pm = fmaxf(t, o);
            acc[k] += fmaxf(pm + bf, 0.f);
        }
    }
    if (!(lane & 1)) {
        int r = lane >> 1;
#pragma unroll
        for (int k = 0; k < 16; k++) P[w][r][k] = acc[k];
    }
    __syncthreads();
    {   // reduce warp partials into shared S2 (no global round-trip)
        int k = tid >> 4, c = tid & 15;
        float s = 0.f;
#pragma unroll
        for (int ww = 0; ww < 8; ww++) s += P[ww][k][c];
        S2[k][c] = s;
    }
    __syncthreads();

    // ===== phase B: layer 2 (identical to standalone k2, fed from S2) =====
    {
        int col = lane & 15;
        float v0 = S2[2 * w + 0][col], v1 = S2[2 * w + 1][col];
#pragma unroll
        for (int m = 1; m < 16; m <<= 1) {
            float o0 = __shfl_xor_sync(~0u, v0, m), o1 = __shfl_xor_sync(~0u, v1, m);
            bool hi = (lane & m) != 0;
            v0 = hi ? o0 - v0 : o0 + v0; v1 = hi ? o1 - v1 : o1 + v1;
        }
        if (lane < 16) { S2[2 * w + 0][col] = v0; S2[2 * w + 1][col] = v1; }
    }
    __syncthreads();
    {
        int row = lane & 15;
        float v0 = S2[row][2 * w + 0], v1 = S2[row][2 * w + 1];
#pragma unroll
        for (int m = 1; m < 16; m <<= 1) {
            float o0 = __shfl_xor_sync(~0u, v0, m), o1 = __shfl_xor_sync(~0u, v1, m);
            bool hi = (lane & m) != 0;
            v0 = hi ? o0 - v0 : o0 + v0; v1 = hi ? o1 - v1 : o1 + v1;
        }
        if (lane < 16) { S2[row][2 * w + 0] = v0; S2[row][2 * w + 1] = v1; }
    }
    __syncthreads();

    int col = lane & 15;
    int hw = lane >> 4;
    float* W2p = &W[0][0][0] + (w * 2 + hw) * 336;   // reuse W region (done)
    ull sp2[8];
#pragma unroll
    for (int i = 0; i < 8; i++) sp2[i] = pack2(S2[2 * i][col], S2[2 * i + 1][col]);

#pragma unroll 1
    for (int ff = 0; ff < 4; ff++) {
        int f = w * 8 + ff * 2 + hw;
        const ull* kt = (const ull*)g_kt2p + (size_t)f * 128 + col;
        ull tp[8];
#pragma unroll
        for (int i = 0; i < 8; i++) tp[i] = fma2(sp2[i], __ldg(kt + i * 16), ZERO2);
#pragma unroll
        for (int mm = 1; mm < 8; mm <<= 1) {
#pragma unroll
            for (int i = 0; i < 8; i++)
                if (!(i & mm)) {
                    ull lo = tp[i], hi = tp[i | mm];
                    tp[i] = fma2(hi, ONE2, lo);
                    tp[i | mm] = fma2(hi, NEG2, lo);
                }
        }
        __syncwarp();
#pragma unroll
        for (int i = 0; i < 8; i++) {
            float a, c;
            unpack2(tp[i], a, c);
            W2p[(2 * i) * 20 + col] = a + c;
            W2p[(2 * i + 1) * 20 + col] = a - c;
        }
        __syncwarp();
        ull up[8];
#pragma unroll
        for (int j = 0; j < 4; j++) {
            float4 v = *(const float4*)(W2p + col * 20 + 4 * j);
            up[2 * j] = pack2(v.x, v.y);
            up[2 * j + 1] = pack2(v.z, v.w);
        }
#pragma unroll
        for (int mm = 1; mm < 8; mm <<= 1) {
#pragma unroll
            for (int i = 0; i < 8; i++)
                if (!(i & mm)) {
                    ull lo = up[i], hi = up[i | mm];
                    up[i] = fma2(hi, ONE2, lo);
                    up[i | mm] = fma2(hi, NEG2, lo);
                }
        }
        float bf = __ldg(bias2 + f);
        float pv[8];
#pragma unroll
        for (int k = 0; k < 8; k++) {
            float A, B;
            unpack2(up[k], A, B);
            float t = A + fabsf(B);
            float o = __shfl_xor_sync(~0u, t, 1);
            float pm = fmaxf(t, o);
            pv[k] = fmaxf(pm + bf, 0.f);
        }
        if (!(lane & 1)) {
            uint4 q;
            __half2 h0 = __floats2half2_rn(pv[0], pv[1]);
            __half2 h1 = __floats2half2_rn(pv[2], pv[3]);
            __half2 h2 = __floats2half2_rn(pv[4], pv[5]);
            __half2 h3 = __floats2half2_rn(pv[6], pv[7]);
            q.x = *(uint32_t*)&h0; q.y = *(uint32_t*)&h1;
            q.z = *(uint32_t*)&h2; q.w = *(uint32_t*)&h3;
            *(uint4*)(g_a + (size_t)b * 4096 + f * 64 + (col >> 1) * 8) = q;
        }
    }
}

// ---------------- K3: FC1 GEMM (warp 32x64, K-chunk 128, K-split 2, 3-stage) --
#define STG3 65536
#define NCH3 16

__global__ void __launch_bounds__(256) k3_fc1() {
    extern __shared__ char smem[];
    uint32_t sb = smem_u32(smem);
    int tid = threadIdx.x, wid = tid >> 5, lane = tid & 31;
    int mt = blockIdx.x, nt = blockIdx.y, ks = blockIdx.z;
    int wm = wid & 3, wn = wid >> 2;

    float acc[2][8][4];
#pragma unroll
    for (int a = 0; a < 2; a++)
#pragma unroll
        for (int b = 0; b < 8; b++)
#pragma unroll
            for (int c = 0; c < 4; c++) acc[a][b][c] = 0.f;

    auto load_chunk = [&](int c, int s) {
        uint32_t st = sb + s * STG3;
        int kc = ks * 2048 + c * 128;
        const char* asrc = (const char*)(g_a + (size_t)mt * 128 * 4096 + kc);
#pragma unroll
        for (int j = 0; j < 8; j++) {
            int u = tid + j * 256, row = u >> 4, ck = u & 15;
            cpasync16(st + swz256(row, ck), asrc + (size_t)row * 8192 + ck * 16);
        }
        const char* bsrc = (const char*)(g_w + (size_t)nt * 128 * 4096 + kc);
#pragma unroll
        for (int j = 0; j < 8; j++) {
            int u = tid + j * 256, row = u >> 4, ck = u & 15;
            cpasync16(st + 32768 + swz256(row, ck), bsrc + (size_t)row * 8192 + ck * 16);
        }
        cp_commit();
    };

    auto load_regs = [&](uint32_t st, int kq, uint32_t ah[2][4], uint32_t bh[4][4]) {
#pragma unroll
        for (int tm = 0; tm < 2; tm++) {
            int row = wm * 32 + tm * 16 + (lane & 15);
            int ck = kq * 2 + (lane >> 4);
            ldsm_x4(st + swz256(row, ck), ah[tm]);
        }
#pragma unroll
        for (int tn = 0; tn < 4; tn++) {
            int n = wn * 64 + tn * 16 + (lane & 7) + ((lane >> 4) << 3);
            int ck = kq * 2 + ((lane >> 3) & 1);
            ldsm_x4(st + 32768 + swz256(n, ck), bh[tn]);
        }
    };

    load_chunk(0, 0);
    load_chunk(1, 1);

    int s = 0, s2 = 2;
    for (int i = 0; i < NCH3; i++) {
        if (i + 1 < NCH3) {
            asm volatile("cp.async.wait_group 1;" ::: "memory");
        } else {
            asm volatile("cp.async.wait_group 0;" ::: "memory");
        }
        __syncthreads();
        if (i + 2 < NCH3) load_chunk(i + 2, s2);

        uint32_t st = sb + s * STG3;
        uint32_t ah[2][2][4], bh[2][4][4];
        load_regs(st, 0, ah[0], bh[0]);
#pragma unroll
        for (int kq = 0; kq < 8; kq++) {
            int cur = kq & 1;
            if (kq < 7) load_regs(st, kq + 1, ah[cur ^ 1], bh[cur ^ 1]);
#pragma unroll
            for (int tm = 0; tm < 2; tm++)
#pragma unroll
                for (int j = 0; j < 8; j++)
                    mma_f16(acc[tm][j], ah[cur][tm], &bh[cur][j >> 1][(j & 1) * 2]);
        }
        s = (s == 2) ? 0 : s + 1;
        s2 = (s2 == 2) ? 0 : s2 + 1;
    }

    int g = lane >> 2, t = lane & 3;
    float* hb = g_h + (size_t)ks * 2048 * 512;
#pragma unroll
    for (int tm = 0; tm < 2; tm++)
#pragma unroll
        for (int j = 0; j < 8; j++) {
            int row0 = mt * 128 + wm * 32 + tm * 16 + g;
            int col = nt * 128 + wn * 64 + j * 8 + 2 * t;
            float* o0 = hb + (size_t)row0 * 512 + col;
            o0[0] = acc[tm][j][0];
            o0[1] = acc[tm][j][1];
            float* o1 = hb + (size_t)(row0 + 8) * 512 + col;
            o1[0] = acc[tm][j][2];
            o1[1] = acc[tm][j][3];
        }
}

// ---------------- K4: FC2 + softmax (sums fc1 partials + bias + relu) ---------
__global__ void __launch_bounds__(256) k4_fc2(const float* __restrict__ fc1b,
                                              const float* __restrict__ w,
                                              const float* __restrict__ fc2b,
                                              float* __restrict__ out) {
    int warp = (blockIdx.x * blockDim.x + threadIdx.x) >> 5;
    int lane = threadIdx.x & 31;
    const float4* h0 = (const float4*)(g_h + (size_t)warp * 512 + lane * 16);
    const float4* h1 = (const float4*)(g_h + 2048 * 512 + (size_t)warp * 512 + lane * 16);
    const float4* b4 = (const float4*)(fc1b + lane * 16);
    float4 xv[4];
#pragma unroll
    for (int j = 0; j < 4; j++) {
        float4 a = h0[j], b = h1[j], c = __ldg(b4 + j);
        xv[j].x = fmaxf(a.x + b.x + c.x, 0.f);
        xv[j].y = fmaxf(a.y + b.y + c.y, 0.f);
        xv[j].z = fmaxf(a.z + b.z + c.z, 0.f);
        xv[j].w = fmaxf(a.w + b.w + c.w, 0.f);
    }
    float l[10];
#pragma unroll
    for (int o = 0; o < 10; o++) {
        const float4* w4 = (const float4*)(w + o * 512 + lane * 16);
        float a = 0.f;
#pragma unroll
        for (int j = 0; j < 4; j++) {
            float4 wv = __ldg(w4 + j);
            a += xv[j].x * wv.x + xv[j].y * wv.y + xv[j].z * wv.z + xv[j].w * wv.w;
        }
#pragma unroll
        for (int m = 16; m >= 1; m >>= 1) a += __shfl_xor_sync(~0u, a, m);
        l[o] = a + __ldg(fc2b + o);
    }
    float mx = l[0];
#pragma unroll
    for (int o = 1; o < 10; o++) mx = fmaxf(mx, l[o]);
    float s = 0.f;
#pragma unroll
    for (int o = 0; o < 10; o++) { l[o] = __expf(l[o] - mx); s += l[o]; }
    float inv = 1.f / s;
    if (lane < 10) out[(size_t)warp * 10 + lane] = l[lane] * inv;
}

// ---------------- launch ------------------------------------------------------
extern "C" void kernel_launch(void* const* d_in, const int* in_sizes, int n_in,
                              void* d_out, int out_size) {
    const float* x    = (const float*)d_in[0];
    const float* f1   = (const float*)d_in[1];
    const float* b1   = (const float*)d_in[2];
    const float* f2   = (const float*)d_in[3];
    const float* b2   = (const float*)d_in[4];
    const float* fc1w = (const float*)d_in[5];
    const float* fc1b = (const float*)d_in[6];
    const float* fc2w = (const float*)d_in[7];
    const float* fc2b = (const float*)d_in[8];
    float* out = (float*)d_out;

    const int smem3 = 3 * STG3;  // 196608 bytes
    cudaFuncSetAttribute(k3_fc1, cudaFuncAttributeMaxDynamicSharedMemorySize, smem3);

    k0_prep<<<2048, 256>>>(f1, f2, fc1w);
    k12_conv<<<2048, 256>>>(x, b1, b2);
    k3_fc1<<<dim3(16, 4, 2), 256, smem3>>>();
    k4_fc2<<<256, 256>>>(fc1b, fc2w, fc2b, out);
}

// round 16
// speedup vs baseline: 1.0195x; 1.0195x over previous
#include <cuda_runtime.h>
#include <cuda_fp16.h>
#include <cstdint>

typedef unsigned long long ull;

// ---------------- scratch ----------------------------------------------------
__device__ float g_kt1p[32 * 1024];              // FWHT2D(filter1)/32768, pair-interleaved
__device__ float g_kt2p[64 * 256];               // FWHT2D(filter2)/4096, pair-interleaved
__device__ float g_s2[2048 * 256];               // layer2 input channel-sum
__device__ __half g_a[2048 * 4096];              // activations (fp16)
__device__ __half g_w[512 * 4096];               // fc1 weights (fp16)
__device__ float g_h[2 * 2048 * 512];            // fc1 partials (2 K-splits)

// ---------------- PTX helpers (baseline ISA only) -----------------------------
__device__ __forceinline__ uint32_t smem_u32(const void* p) {
    uint32_t a;
    asm("{ .reg .u64 t; cvta.to.shared.u64 t, %1; cvt.u32.u64 %0, t; }" : "=r"(a) : "l"(p));
    return a;
}
__device__ __forceinline__ void cpasync16(uint32_t dst, const void* src) {
    asm volatile("cp.async.cg.shared.global [%0], [%1], 16;" :: "r"(dst), "l"(src));
}
__device__ __forceinline__ void cp_commit() {
    asm volatile("cp.async.commit_group;" ::: "memory");
}
__device__ __forceinline__ void ldsm_x4(uint32_t addr, uint32_t* r) {
    asm volatile("ldmatrix.sync.aligned.m8n8.x4.shared.b16 {%0,%1,%2,%3}, [%4];"
                 : "=r"(r[0]), "=r"(r[1]), "=r"(r[2]), "=r"(r[3]) : "r"(addr));
}
__device__ __forceinline__ void mma_f16(float* d, const uint32_t* a, const uint32_t* b) {
    asm volatile(
        "mma.sync.aligned.m16n8k16.row.col.f32.f16.f16.f32 "
        "{%0,%1,%2,%3}, {%4,%5,%6,%7}, {%8,%9}, {%0,%1,%2,%3};"
        : "+f"(d[0]), "+f"(d[1]), "+f"(d[2]), "+f"(d[3])
        : "r"(a[0]), "r"(a[1]), "r"(a[2]), "r"(a[3]), "r"(b[0]), "r"(b[1]));
}
__device__ __forceinline__ ull pack2(float lo, float hi) {
    ull r; asm("mov.b64 %0, {%1,%2};" : "=l"(r) : "f"(lo), "f"(hi)); return r;
}
__device__ __forceinline__ void unpack2(ull v, float& lo, float& hi) {
    asm("mov.b64 {%0,%1}, %2;" : "=f"(lo), "=f"(hi) : "l"(v));
}
__device__ __forceinline__ ull fma2(ull a, ull b, ull c) {
    ull r; asm("fma.rn.f32x2 %0, %1, %2, %3;" : "=l"(r) : "l"(a), "l"(b), "l"(c)); return r;
}
#define ONE2 0x3F8000003F800000ULL
#define NEG2 0xBF800000BF800000ULL
#define ZERO2 0x0000000000000000ULL

// swizzled byte offset within a 256B row (K-chunk 128 fp16): ck in 16B units 0..15
__device__ __forceinline__ uint32_t swz256(int row, int ck) {
    return row * 256 + (ck >> 3) * 128 + (((ck & 7) ^ (row & 7)) * 16);
}

// ---------------- K0: filter transform (pair-interleaved) + fc1 w -> fp16 -----
__global__ void k0_prep(const float* __restrict__ f1, const float* __restrict__ f2,
                        const float* __restrict__ W) {
    int gid = blockIdx.x * 256 + threadIdx.x;
    {
        int i = gid * 4;
        float4 v = *(const float4*)(W + i);
        *(__half2*)(g_w + i) = __floats2half2_rn(v.x, v.y);
        *(__half2*)(g_w + i + 2) = __floats2half2_rn(v.z, v.w);
    }
    if (gid < 32 * 1024) {
        int f = gid >> 10, ij = gid & 1023, row = ij >> 5, col = ij & 31;
        float s = 0.f;
        for (int p = 0; p < 3; p++)
            for (int q = 0; q < 3; q++) {
                float v = f1[f * 9 + p * 3 + q];
                s += ((__popc(row & p) + __popc(col & q)) & 1) ? -v : v;
            }
        g_kt1p[(f * 16 + (row >> 1)) * 64 + col * 2 + (row & 1)] = s * (1.0f / 32768.0f);
    } else if (gid < 32 * 1024 + 64 * 256) {
        int k = gid - 32 * 1024;
        int f = k >> 8, ij = k & 255, row = ij >> 4, col = ij & 15;
        float s = 0.f;
        for (int p = 0; p < 3; p++)
            for (int q = 0; q < 3; q++) {
                float v = f2[f * 9 + p * 3 + q];
                s += ((__popc(row & p) + __popc(col & q)) & 1) ? -v : v;
            }
        g_kt2p[(f * 8 + (row >> 1)) * 32 + col * 2 + (row & 1)] = s * (1.0f / 4096.0f);
    }
}

// ---------------- K1: layer 1 fused (packed f32x2, packed kt loads) -----------
__global__ void __launch_bounds__(256) k1_layer1(const float* __restrict__ x,
                                                 const float* __restrict__ bias1) {
    int b = blockIdx.x, tid = threadIdx.x;
    int w = tid >> 5, lane = tid & 31;
    __shared__ __align__(16) float W[8][32][36];
    __shared__ float P[8][16][16];
    float (*S)[33] = (float(*)[33]) & W[0][0][0];

    {   // channel sum
        const float* xb = x + (size_t)b * 3072;
        int base = tid * 4, r = base >> 5, c = base & 31;
        float4 v0 = *(const float4*)(xb + base);
        float4 v1 = *(const float4*)(xb + 1024 + base);
        float4 v2 = *(const float4*)(xb + 2048 + base);
        S[r][c + 0] = v0.x + v1.x + v2.x;
        S[r][c + 1] = v0.y + v1.y + v2.y;
        S[r][c + 2] = v0.z + v1.z + v2.z;
        S[r][c + 3] = v0.w + v1.w + v2.w;
    }
    __syncthreads();
    {
        float v0 = S[w * 4 + 0][lane], v1 = S[w * 4 + 1][lane];
        float v2 = S[w * 4 + 2][lane], v3 = S[w * 4 + 3][lane];
#pragma unroll
        for (int m = 1; m < 32; m <<= 1) {
            float o0 = __shfl_xor_sync(~0u, v0, m), o1 = __shfl_xor_sync(~0u, v1, m);
            float o2 = __shfl_xor_sync(~0u, v2, m), o3 = __shfl_xor_sync(~0u, v3, m);
            bool hi = (lane & m) != 0;
            v0 = hi ? o0 - v0 : o0 + v0; v1 = hi ? o1 - v1 : o1 + v1;
            v2 = hi ? o2 - v2 : o2 + v2; v3 = hi ? o3 - v3 : o3 + v3;
        }
        S[w * 4 + 0][lane] = v0; S[w * 4 + 1][lane] = v1;
        S[w * 4 + 2][lane] = v2; S[w * 4 + 3][lane] = v3;
    }
    __syncthreads();
    {
        float v0 = S[lane][w * 4 + 0], v1 = S[lane][w * 4 + 1];
        float v2 = S[lane][w * 4 + 2], v3 = S[lane][w * 4 + 3];
#pragma unroll
        for (int m = 1; m < 32; m <<= 1) {
            float o0 = __shfl_xor_sync(~0u, v0, m), o1 = __shfl_xor_sync(~0u, v1, m);
            float o2 = __shfl_xor_sync(~0u, v2, m), o3 = __shfl_xor_sync(~0u, v3, m);
            bool hi = (lane & m) != 0;
            v0 = hi ? o0 - v0 : o0 + v0; v1 = hi ? o1 - v1 : o1 + v1;
            v2 = hi ? o2 - v2 : o2 + v2; v3 = hi ? o3 - v3 : o3 + v3;
        }
        S[lane][w * 4 + 0] = v0; S[lane][w * 4 + 1] = v1;
        S[lane][w * 4 + 2] = v2; S[lane][w * 4 + 3] = v3;
    }
    __syncthreads();

    ull sp[16];
#pragma unroll
    for (int i = 0; i < 16; i++) sp[i] = pack2(S[2 * i][lane], S[2 * i + 1][lane]);
    __syncthreads();

    float acc[16];
#pragma unroll
    for (int k = 0; k < 16; k++) acc[k] = 0.f;
    float* Wp = &W[w][0][0];

#pragma unroll 1
    for (int ff = 0; ff < 4; ff++) {
        int f = w + ff * 8;
        const ull* kt = (const ull*)g_kt1p + (size_t)f * 512 + lane;
        ull tp[16];
#pragma unroll
        for (int i = 0; i < 16; i++) tp[i] = fma2(sp[i], __ldg(kt + i * 32), ZERO2);
#pragma unroll
        for (int mm = 1; mm < 16; mm <<= 1) {
#pragma unroll
            for (int i = 0; i < 16; i++)
                if (!(i & mm)) {
                    ull lo = tp[i], hi = tp[i | mm];
                    tp[i] = fma2(hi, ONE2, lo);
                    tp[i | mm] = fma2(hi, NEG2, lo);
                }
        }
        __syncwarp();
#pragma unroll
        for (int i = 0; i < 16; i++) {
            float a, c;
            unpack2(tp[i], a, c);
            Wp[(2 * i) * 36 + lane] = a + c;
            Wp[(2 * i + 1) * 36 + lane] = a - c;
        }
        __syncwarp();
        ull up[16];
#pragma unroll
        for (int j = 0; j < 8; j++) {
            float4 v = *(const float4*)(Wp + lane * 36 + 4 * j);
            up[2 * j] = pack2(v.x, v.y);
            up[2 * j + 1] = pack2(v.z, v.w);
        }
#pragma unroll
        for (int mm = 1; mm < 16; mm <<= 1) {
#pragma unroll
            for (int i = 0; i < 16; i++)
                if (!(i & mm)) {
                    ull lo = up[i], hi = up[i | mm];
                    up[i] = fma2(hi, ONE2, lo);
                    up[i | mm] = fma2(hi, NEG2, lo);
                }
        }
        float bf = __ldg(bias1 + f);
#pragma unroll
        for (int k = 0; k < 16; k++) {
            float A, B;
            unpack2(up[k], A, B);
            float t = A + fabsf(B);
            float o = __shfl_xor_sync(~0u, t, 1);
            float pm = fmaxf(t, o);
            acc[k] += fmaxf(pm + bf, 0.f);
        }
    }
    if (!(lane & 1)) {
        int r = lane >> 1;
#pragma unroll
        for (int k = 0; k < 16; k++) P[w][r][k] = acc[k];
    }
    __syncthreads();
    {
        int k = tid >> 4, c = tid & 15;
        float s = 0.f;
#pragma unroll
        for (int ww = 0; ww < 8; ww++) s += P[ww][k][c];
        g_s2[(size_t)b * 256 + tid] = s;
    }
}

// ---------------- K2: layer 2 fused, 2 images per CTA --------------------------
__global__ void __launch_bounds__(256) k2_layer2(const float* __restrict__ bias2) {
    int b0 = blockIdx.x * 2, tid = threadIdx.x;
    int w = tid >> 5, lane = tid & 31;
    __shared__ float S[2][16][17];
    __shared__ __align__(16) float W2[16 * 336];

    S[0][tid >> 4][tid & 15] = g_s2[(size_t)b0 * 256 + tid];
    S[1][tid >> 4][tid & 15] = g_s2[(size_t)(b0 + 1) * 256 + tid];
    __syncthreads();

    int hw = lane >> 4;        // image selector
    int col = lane & 15;
    {
        float v0 = S[hw][2 * w + 0][col], v1 = S[hw][2 * w + 1][col];
#pragma unroll
        for (int m = 1; m < 16; m <<= 1) {
            float o0 = __shfl_xor_sync(~0u, v0, m), o1 = __shfl_xor_sync(~0u, v1, m);
            bool hi = (lane & m) != 0;
            v0 = hi ? o0 - v0 : o0 + v0; v1 = hi ? o1 - v1 : o1 + v1;
        }
        S[hw][2 * w + 0][col] = v0; S[hw][2 * w + 1][col] = v1;
    }
    __syncthreads();
    {
        int row = lane & 15;
        float v0 = S[hw][row][2 * w + 0], v1 = S[hw][row][2 * w + 1];
#pragma unroll
        for (int m = 1; m < 16; m <<= 1) {
            float o0 = __shfl_xor_sync(~0u, v0, m), o1 = __shfl_xor_sync(~0u, v1, m);
            bool hi = (lane & m) != 0;
            v0 = hi ? o0 - v0 : o0 + v0; v1 = hi ? o1 - v1 : o1 + v1;
        }
        S[hw][row][2 * w + 0] = v0; S[hw][row][2 * w + 1] = v1;
    }
    __syncthreads();

    float* W2p = &W2[(w * 2 + hw) * 336];
    ull sp[8];
#pragma unroll
    for (int i = 0; i < 8; i++) sp[i] = pack2(S[hw][2 * i][col], S[hw][2 * i + 1][col]);

#pragma unroll 1
    for (int ff = 0; ff < 8; ff++) {
        int f = w * 8 + ff;
        const ull* kt = (const ull*)g_kt2p + (size_t)f * 128 + col;
        ull tp[8];
#pragma unroll
        for (int i = 0; i < 8; i++) tp[i] = fma2(sp[i], __ldg(kt + i * 16), ZERO2);
#pragma unroll
        for (int mm = 1; mm < 8; mm <<= 1) {
#pragma unroll
            for (int i = 0; i < 8; i++)
                if (!(i & mm)) {
                    ull lo = tp[i], hi = tp[i | mm];
                    tp[i] = fma2(hi, ONE2, lo);
                    tp[i | mm] = fma2(hi, NEG2, lo);
                }
        }
        __syncwarp();
#pragma unroll
        for (int i = 0; i < 8; i++) {
            float a, c;
            unpack2(tp[i], a, c);
            W2p[(2 * i) * 20 + col] = a + c;
            W2p[(2 * i + 1) * 20 + col] = a - c;
        }
        __syncwarp();
        ull up[8];
#pragma unroll
        for (int j = 0; j < 4; j++) {
            float4 v = *(const float4*)(W2p + col * 20 + 4 * j);
            up[2 * j] = pack2(v.x, v.y);
            up[2 * j + 1] = pack2(v.z, v.w);
        }
#pragma unroll
        for (int mm = 1; mm < 8; mm <<= 1) {
#pragma unroll
            for (int i = 0; i < 8; i++)
                if (!(i & mm)) {
                    ull lo = up[i], hi = up[i | mm];
                    up[i] = fma2(hi, ONE2, lo);
                    up[i | mm] = fma2(hi, NEG2, lo);
                }
        }
        float bf = __ldg(bias2 + f);
        float pv[8];
#pragma unroll
        for (int k = 0; k < 8; k++) {
            float A, B;
            unpack2(up[k], A, B);
            float t = A + fabsf(B);
            float o = __shfl_xor_sync(~0u, t, 1);
            float pm = fmaxf(t, o);
            pv[k] = fmaxf(pm + bf, 0.f);
        }
        if (!(lane & 1)) {
            uint4 q;
            __half2 h0 = __floats2half2_rn(pv[0], pv[1]);
            __half2 h1 = __floats2half2_rn(pv[2], pv[3]);
            __half2 h2 = __floats2half2_rn(pv[4], pv[5]);
            __half2 h3 = __floats2half2_rn(pv[6], pv[7]);
            q.x = *(uint32_t*)&h0; q.y = *(uint32_t*)&h1;
            q.z = *(uint32_t*)&h2; q.w = *(uint32_t*)&h3;
            *(uint4*)(g_a + (size_t)(b0 + hw) * 4096 + f * 64 + (col >> 1) * 8) = q;
        }
    }
}

// ---------------- K3: FC1 GEMM (warp 32x64, K-chunk 128, K-split 2, 3-stage) --
#define STG3 65536
#define NCH3 16

__global__ void __launch_bounds__(256) k3_fc1() {
    extern __shared__ char smem[];
    uint32_t sb = smem_u32(smem);
    int tid = threadIdx.x, wid = tid >> 5, lane = tid & 31;
    int mt = blockIdx.x, nt = blockIdx.y, ks = blockIdx.z;
    int wm = wid & 3, wn = wid >> 2;

    float acc[2][8][4];
#pragma unroll
    for (int a = 0; a < 2; a++)
#pragma unroll
        for (int b = 0; b < 8; b++)
#pragma unroll
            for (int c = 0; c < 4; c++) acc[a][b][c] = 0.f;

    auto load_chunk = [&](int c, int s) {
        uint32_t st = sb + s * STG3;
        int kc = ks * 2048 + c * 128;
        const char* asrc = (const char*)(g_a + (size_t)mt * 128 * 4096 + kc);
#pragma unroll
        for (int j = 0; j < 8; j++) {
            int u = tid + j * 256, row = u >> 4, ck = u & 15;
            cpasync16(st + swz256(row, ck), asrc + (size_t)row * 8192 + ck * 16);
        }
        const char* bsrc = (const char*)(g_w + (size_t)nt * 128 * 4096 + kc);
#pragma unroll
        for (int j = 0; j < 8; j++) {
            int u = tid + j * 256, row = u >> 4, ck = u & 15;
            cpasync16(st + 32768 + swz256(row, ck), bsrc + (size_t)row * 8192 + ck * 16);
        }
        cp_commit();
    };

    auto load_regs = [&](uint32_t st, int kq, uint32_t ah[2][4], uint32_t bh[4][4]) {
#pragma unroll
        for (int tm = 0; tm < 2; tm++) {
            int row = wm * 32 + tm * 16 + (lane & 15);
            int ck = kq * 2 + (lane >> 4);
            ldsm_x4(st + swz256(row, ck), ah[tm]);
        }
#pragma unroll
        for (int tn = 0; tn < 4; tn++) {
            int n = wn * 64 + tn * 16 + (lane & 7) + ((lane >> 4) << 3);
            int ck = kq * 2 + ((lane >> 3) & 1);
            ldsm_x4(st + 32768 + swz256(n, ck), bh[tn]);
        }
    };

    load_chunk(0, 0);
    load_chunk(1, 1);

    int s = 0, s2 = 2;
    for (int i = 0; i < NCH3; i++) {
        if (i + 1 < NCH3) {
            asm volatile("cp.async.wait_group 1;" ::: "memory");
        } else {
            asm volatile("cp.async.wait_group 0;" ::: "memory");
        }
        __syncthreads();
        if (i + 2 < NCH3) load_chunk(i + 2, s2);

        uint32_t st = sb + s * STG3;
        uint32_t ah[2][2][4], bh[2][4][4];
        load_regs(st, 0, ah[0], bh[0]);
#pragma unroll
        for (int kq = 0; kq < 8; kq++) {
            int cur = kq & 1;
            if (kq < 7) load_regs(st, kq + 1, ah[cur ^ 1], bh[cur ^ 1]);
#pragma unroll
            for (int tm = 0; tm < 2; tm++)
#pragma unroll
                for (int j = 0; j < 8; j++)
                    mma_f16(acc[tm][j], ah[cur][tm], &bh[cur][j >> 1][(j & 1) * 2]);
        }
        s = (s == 2) ? 0 : s + 1;
        s2 = (s2 == 2) ? 0 : s2 + 1;
    }

    int g = lane >> 2, t = lane & 3;
    float* hb = g_h + (size_t)ks * 2048 * 512;
#pragma unroll
    for (int tm = 0; tm < 2; tm++)
#pragma unroll
        for (int j = 0; j < 8; j++) {
            int row0 = mt * 128 + wm * 32 + tm * 16 + g;
            int col = nt * 128 + wn * 64 + j * 8 + 2 * t;
            float* o0 = hb + (size_t)row0 * 512 + col;
            o0[0] = acc[tm][j][0];
            o0[1] = acc[tm][j][1];
            float* o1 = hb + (size_t)(row0 + 8) * 512 + col;
            o1[0] = acc[tm][j][2];
            o1[1] = acc[tm][j][3];
        }
}

// ---------------- K4: FC2 + softmax (MLP-restructured) ------------------------
__global__ void __launch_bounds__(256) k4_fc2(const float* __restrict__ fc1b,
                                              const float* __restrict__ w,
                                              const float* __restrict__ fc2b,
                                              float* __restrict__ out) {
    int warp = (blockIdx.x * blockDim.x + threadIdx.x) >> 5;
    int lane = threadIdx.x & 31;
    const float4* h0 = (const float4*)(g_h + (size_t)warp * 512 + lane * 16);
    const float4* h1 = (const float4*)(g_h + 2048 * 512 + (size_t)warp * 512 + lane * 16);
    const float4* b4 = (const float4*)(fc1b + lane * 16);
    float4 xv[4];
#pragma unroll
    for (int j = 0; j < 4; j++) {
        float4 a = h0[j], b = h1[j], c = __ldg(b4 + j);
        xv[j].x = fmaxf(a.x + b.x + c.x, 0.f);
        xv[j].y = fmaxf(a.y + b.y + c.y, 0.f);
        xv[j].z = fmaxf(a.z + b.z + c.z, 0.f);
        xv[j].w = fmaxf(a.w + b.w + c.w, 0.f);
    }
    // all 40 weight loads issued with no inter-dependency (j outer, o inner):
    float l[10];
#pragma unroll
    for (int o = 0; o < 10; o++) l[o] = 0.f;
#pragma unroll
    for (int j = 0; j < 4; j++) {
#pragma unroll
        for (int o = 0; o < 10; o++) {
            float4 wv = __ldg((const float4*)(w + o * 512 + lane * 16) + j);
            l[o] += xv[j].x * wv.x + xv[j].y * wv.y + xv[j].z * wv.z + xv[j].w * wv.w;
        }
    }
    // 10 independent reduction chains
#pragma unroll
    for (int m = 16; m >= 1; m >>= 1)
#pragma unroll
        for (int o = 0; o < 10; o++) l[o] += __shfl_xor_sync(~0u, l[o], m);
#pragma unroll
    for (int o = 0; o < 10; o++) l[o] += __ldg(fc2b + o);

    float mx = l[0];
#pragma unroll
    for (int o = 1; o < 10; o++) mx = fmaxf(mx, l[o]);
    float s = 0.f;
#pragma unroll
    for (int o = 0; o < 10; o++) { l[o] = __expf(l[o] - mx); s += l[o]; }
    float inv = 1.f / s;
    if (lane < 10) out[(size_t)warp * 10 + lane] = l[lane] * inv;
}

// ---------------- launch ------------------------------------------------------
extern "C" void kernel_launch(void* const* d_in, const int* in_sizes, int n_in,
                              void* d_out, int out_size) {
    const float* x    = (const float*)d_in[0];
    const float* f1   = (const float*)d_in[1];
    const float* b1   = (const float*)d_in[2];
    const float* f2   = (const float*)d_in[3];
    const float* b2   = (const float*)d_in[4];
    const float* fc1w = (const float*)d_in[5];
    const float* fc1b = (const float*)d_in[6];
    const float* fc2w = (const float*)d_in[7];
    const float* fc2b = (const float*)d_in[8];
    float* out = (float*)d_out;

    const int smem3 = 3 * STG3;  // 196608 bytes
    cudaFuncSetAttribute(k3_fc1, cudaFuncAttributeMaxDynamicSharedMemorySize, smem3);

    k0_prep<<<2048, 256>>>(f1, f2, fc1w);
    k1_layer1<<<2048, 256>>>(x, b1);
    k2_layer2<<<1024, 256>>>(b2);
    k3_fc1<<<dim3(16, 4, 2), 256, smem3>>>();
    k4_fc2<<<256, 256>>>(fc1b, fc2w, fc2b, out);
}

// round 17
// speedup vs baseline: 1.0220x; 1.0024x over previous
#include <cuda_runtime.h>
#include <cuda_fp16.h>
#include <cstdint>

typedef unsigned long long ull;

// ---------------- scratch ----------------------------------------------------
__device__ float g_kt1p[32 * 1024];              // FWHT2D(filter1)/32768, pair-interleaved
__device__ float g_kt2p[64 * 256];               // FWHT2D(filter2)/4096, pair-interleaved
__device__ float g_s2[2048 * 256];               // layer2 input channel-sum
__device__ __half g_a[2048 * 4096];              // activations (fp16)
__device__ __half g_w[512 * 4096];               // fc1 weights (fp16)
__device__ float g_h[2 * 2048 * 512];            // fc1 partials (2 K-splits)

// ---------------- side stream + events (created once at load; no device mem) --
namespace {
struct StreamInit {
    cudaStream_t s;
    cudaEvent_t evFork, evJoin;
    StreamInit() {
        cudaStreamCreateWithFlags(&s, cudaStreamNonBlocking);
        cudaEventCreateWithFlags(&evFork, cudaEventDisableTiming);
        cudaEventCreateWithFlags(&evJoin, cudaEventDisableTiming);
    }
};
StreamInit g_si;
}

// ---------------- PTX helpers (baseline ISA only) -----------------------------
__device__ __forceinline__ uint32_t smem_u32(const void* p) {
    uint32_t a;
    asm("{ .reg .u64 t; cvta.to.shared.u64 t, %1; cvt.u32.u64 %0, t; }" : "=r"(a) : "l"(p));
    return a;
}
__device__ __forceinline__ void cpasync16(uint32_t dst, const void* src) {
    asm volatile("cp.async.cg.shared.global [%0], [%1], 16;" :: "r"(dst), "l"(src));
}
__device__ __forceinline__ void cp_commit() {
    asm volatile("cp.async.commit_group;" ::: "memory");
}
__device__ __forceinline__ void ldsm_x4(uint32_t addr, uint32_t* r) {
    asm volatile("ldmatrix.sync.aligned.m8n8.x4.shared.b16 {%0,%1,%2,%3}, [%4];"
                 : "=r"(r[0]), "=r"(r[1]), "=r"(r[2]), "=r"(r[3]) : "r"(addr));
}
__device__ __forceinline__ void mma_f16(float* d, const uint32_t* a, const uint32_t* b) {
    asm volatile(
        "mma.sync.aligned.m16n8k16.row.col.f32.f16.f16.f32 "
        "{%0,%1,%2,%3}, {%4,%5,%6,%7}, {%8,%9}, {%0,%1,%2,%3};"
        : "+f"(d[0]), "+f"(d[1]), "+f"(d[2]), "+f"(d[3])
        : "r"(a[0]), "r"(a[1]), "r"(a[2]), "r"(a[3]), "r"(b[0]), "r"(b[1]));
}
__device__ __forceinline__ ull pack2(float lo, float hi) {
    ull r; asm("mov.b64 %0, {%1,%2};" : "=l"(r) : "f"(lo), "f"(hi)); return r;
}
__device__ __forceinline__ void unpack2(ull v, float& lo, float& hi) {
    asm("mov.b64 {%0,%1}, %2;" : "=f"(lo), "=f"(hi) : "l"(v));
}
__device__ __forceinline__ ull fma2(ull a, ull b, ull c) {
    ull r; asm("fma.rn.f32x2 %0, %1, %2, %3;" : "=l"(r) : "l"(a), "l"(b), "l"(c)); return r;
}
#define ONE2 0x3F8000003F800000ULL
#define NEG2 0xBF800000BF800000ULL
#define ZERO2 0x0000000000000000ULL

// swizzled byte offset within a 256B row (K-chunk 128 fp16): ck in 16B units 0..15
__device__ __forceinline__ uint32_t swz256(int row, int ck) {
    return row * 256 + (ck >> 3) * 128 + (((ck & 7) ^ (row & 7)) * 16);
}

// ---------------- KF: filter transforms only (needed by k1/k2) ----------------
__global__ void kf_filters(const float* __restrict__ f1, const float* __restrict__ f2) {
    int gid = blockIdx.x * 256 + threadIdx.x;
    if (gid < 32 * 1024) {
        int f = gid >> 10, ij = gid & 1023, row = ij >> 5, col = ij & 31;
        float s = 0.f;
        for (int p = 0; p < 3; p++)
            for (int q = 0; q < 3; q++) {
                float v = f1[f * 9 + p * 3 + q];
                s += ((__popc(row & p) + __popc(col & q)) & 1) ? -v : v;
            }
        g_kt1p[(f * 16 + (row >> 1)) * 64 + col * 2 + (row & 1)] = s * (1.0f / 32768.0f);
    } else if (gid < 32 * 1024 + 64 * 256) {
        int k = gid - 32 * 1024;
        int f = k >> 8, ij = k & 255, row = ij >> 4, col = ij & 15;
        float s = 0.f;
        for (int p = 0; p < 3; p++)
            for (int q = 0; q < 3; q++) {
                float v = f2[f * 9 + p * 3 + q];
                s += ((__popc(row & p) + __popc(col & q)) & 1) ? -v : v;
            }
        g_kt2p[(f * 8 + (row >> 1)) * 32 + col * 2 + (row & 1)] = s * (1.0f / 4096.0f);
    }
}

// ---------------- KW: fc1 weights fp32 -> fp16 (needed only by k3) ------------
__global__ void kw_conv(const float* __restrict__ W) {
    int i = (blockIdx.x * 256 + threadIdx.x) * 4;
    float4 v = *(const float4*)(W + i);
    *(__half2*)(g_w + i) = __floats2half2_rn(v.x, v.y);
    *(__half2*)(g_w + i + 2) = __floats2half2_rn(v.z, v.w);
}

// ---------------- K1: layer 1 fused (packed f32x2, packed kt loads) -----------
__global__ void __launch_bounds__(256) k1_layer1(const float* __restrict__ x,
                                                 const float* __restrict__ bias1) {
    int b = blockIdx.x, tid = threadIdx.x;
    int w = tid >> 5, lane = tid & 31;
    __shared__ __align__(16) float W[8][32][36];
    __shared__ float P[8][16][16];
    float (*S)[33] = (float(*)[33]) & W[0][0][0];

    {   // channel sum
        const float* xb = x + (size_t)b * 3072;
        int base = tid * 4, r = base >> 5, c = base & 31;
        float4 v0 = *(const float4*)(xb + base);
        float4 v1 = *(const float4*)(xb + 1024 + base);
        float4 v2 = *(const float4*)(xb + 2048 + base);
        S[r][c + 0] = v0.x + v1.x + v2.x;
        S[r][c + 1] = v0.y + v1.y + v2.y;
        S[r][c + 2] = v0.z + v1.z + v2.z;
        S[r][c + 3] = v0.w + v1.w + v2.w;
    }
    __syncthreads();
    {
        float v0 = S[w * 4 + 0][lane], v1 = S[w * 4 + 1][lane];
        float v2 = S[w * 4 + 2][lane], v3 = S[w * 4 + 3][lane];
#pragma unroll
        for (int m = 1; m < 32; m <<= 1) {
            float o0 = __shfl_xor_sync(~0u, v0, m), o1 = __shfl_xor_sync(~0u, v1, m);
            float o2 = __shfl_xor_sync(~0u, v2, m), o3 = __shfl_xor_sync(~0u, v3, m);
            bool hi = (lane & m) != 0;
            v0 = hi ? o0 - v0 : o0 + v0; v1 = hi ? o1 - v1 : o1 + v1;
            v2 = hi ? o2 - v2 : o2 + v2; v3 = hi ? o3 - v3 : o3 + v3;
        }
        S[w * 4 + 0][lane] = v0; S[w * 4 + 1][lane] = v1;
        S[w * 4 + 2][lane] = v2; S[w * 4 + 3][lane] = v3;
    }
    __syncthreads();
    {
        float v0 = S[lane][w * 4 + 0], v1 = S[lane][w * 4 + 1];
        float v2 = S[lane][w * 4 + 2], v3 = S[lane][w * 4 + 3];
#pragma unroll
        for (int m = 1; m < 32; m <<= 1) {
            float o0 = __shfl_xor_sync(~0u, v0, m), o1 = __shfl_xor_sync(~0u, v1, m);
            float o2 = __shfl_xor_sync(~0u, v2, m), o3 = __shfl_xor_sync(~0u, v3, m);
            bool hi = (lane & m) != 0;
            v0 = hi ? o0 - v0 : o0 + v0; v1 = hi ? o1 - v1 : o1 + v1;
            v2 = hi ? o2 - v2 : o2 + v2; v3 = hi ? o3 - v3 : o3 + v3;
        }
        S[lane][w * 4 + 0] = v0; S[lane][w * 4 + 1] = v1;
        S[lane][w * 4 + 2] = v2; S[lane][w * 4 + 3] = v3;
    }
    __syncthreads();

    ull sp[16];
#pragma unroll
    for (int i = 0; i < 16; i++) sp[i] = pack2(S[2 * i][lane], S[2 * i + 1][lane]);
    __syncthreads();

    float acc[16];
#pragma unroll
    for (int k = 0; k < 16; k++) acc[k] = 0.f;
    float* Wp = &W[w][0][0];

#pragma unroll 1
    for (int ff = 0; ff < 4; ff++) {
        int f = w + ff * 8;
        const ull* kt = (const ull*)g_kt1p + (size_t)f * 512 + lane;
        ull tp[16];
#pragma unroll
        for (int i = 0; i < 16; i++) tp[i] = fma2(sp[i], __ldg(kt + i * 32), ZERO2);
#pragma unroll
        for (int mm = 1; mm < 16; mm <<= 1) {
#pragma unroll
            for (int i = 0; i < 16; i++)
                if (!(i & mm)) {
                    ull lo = tp[i], hi = tp[i | mm];
                    tp[i] = fma2(hi, ONE2, lo);
                    tp[i | mm] = fma2(hi, NEG2, lo);
                }
        }
        __syncwarp();
#pragma unroll
        for (int i = 0; i < 16; i++) {
            float a, c;
            unpack2(tp[i], a, c);
            Wp[(2 * i) * 36 + lane] = a + c;
            Wp[(2 * i + 1) * 36 + lane] = a - c;
        }
        __syncwarp();
        ull up[16];
#pragma unroll
        for (int j = 0; j < 8; j++) {
            float4 v = *(const float4*)(Wp + lane * 36 + 4 * j);
            up[2 * j] = pack2(v.x, v.y);
            up[2 * j + 1] = pack2(v.z, v.w);
        }
#pragma unroll
        for (int mm = 1; mm < 16; mm <<= 1) {
#pragma unroll
            for (int i = 0; i < 16; i++)
                if (!(i & mm)) {
                    ull lo = up[i], hi = up[i | mm];
                    up[i] = fma2(hi, ONE2, lo);
                    up[i | mm] = fma2(hi, NEG2, lo);
                }
        }
        float bf = __ldg(bias1 + f);
#pragma unroll
        for (int k = 0; k < 16; k++) {
            float A, B;
            unpack2(up[k], A, B);
            float t = A + fabsf(B);
            float o = __shfl_xor_sync(~0u, t, 1);
            float pm = fmaxf(t, o);
            acc[k] += fmaxf(pm + bf, 0.f);
        }
    }
    if (!(lane & 1)) {
        int r = lane >> 1;
#pragma unroll
        for (int k = 0; k < 16; k++) P[w][r][k] = acc[k];
    }
    __syncthreads();
    {
        int k = tid >> 4, c = tid & 15;
        float s = 0.f;
#pragma unroll
        for (int ww = 0; ww < 8; ww++) s += P[ww][k][c];
        g_s2[(size_t)b * 256 + tid] = s;
    }
}

// ---------------- K2: layer 2 fused, 2 images per CTA --------------------------
__global__ void __launch_bounds__(256) k2_layer2(const float* __restrict__ bias2) {
    int b0 = blockIdx.x * 2, tid = threadIdx.x;
    int w = tid >> 5, lane = tid & 31;
    __shared__ float S[2][16][17];
    __shared__ __align__(16) float W2[16 * 336];

    S[0][tid >> 4][tid & 15] = g_s2[(size_t)b0 * 256 + tid];
    S[1][tid >> 4][tid & 15] = g_s2[(size_t)(b0 + 1) * 256 + tid];
    __syncthreads();

    int hw = lane >> 4;        // image selector
    int col = lane & 15;
    {
        float v0 = S[hw][2 * w + 0][col], v1 = S[hw][2 * w + 1][col];
#pragma unroll
        for (int m = 1; m < 16; m <<= 1) {
            float o0 = __shfl_xor_sync(~0u, v0, m), o1 = __shfl_xor_sync(~0u, v1, m);
            bool hi = (lane & m) != 0;
            v0 = hi ? o0 - v0 : o0 + v0; v1 = hi ? o1 - v1 : o1 + v1;
        }
        S[hw][2 * w + 0][col] = v0; S[hw][2 * w + 1][col] = v1;
    }
    __syncthreads();
    {
        int row = lane & 15;
        float v0 = S[hw][row][2 * w + 0], v1 = S[hw][row][2 * w + 1];
#pragma unroll
        for (int m = 1; m < 16; m <<= 1) {
            float o0 = __shfl_xor_sync(~0u, v0, m), o1 = __shfl_xor_sync(~0u, v1, m);
            bool hi = (lane & m) != 0;
            v0 = hi ? o0 - v0 : o0 + v0; v1 = hi ? o1 - v1 : o1 + v1;
        }
        S[hw][row][2 * w + 0] = v0; S[hw][row][2 * w + 1] = v1;
    }
    __syncthreads();

    float* W2p = &W2[(w * 2 + hw) * 336];
    ull sp[8];
#pragma unroll
    for (int i = 0; i < 8; i++) sp[i] = pack2(S[hw][2 * i][col], S[hw][2 * i + 1][col]);

#pragma unroll 1
    for (int ff = 0; ff < 8; ff++) {
        int f = w * 8 + ff;
        const ull* kt = (const ull*)g_kt2p + (size_t)f * 128 + col;
        ull tp[8];
#pragma unroll
        for (int i = 0; i < 8; i++) tp[i] = fma2(sp[i], __ldg(kt + i * 16), ZERO2);
#pragma unroll
        for (int mm = 1; mm < 8; mm <<= 1) {
#pragma unroll
            for (int i = 0; i < 8; i++)
                if (!(i & mm)) {
                    ull lo = tp[i], hi = tp[i | mm];
                    tp[i] = fma2(hi, ONE2, lo);
                    tp[i | mm] = fma2(hi, NEG2, lo);
                }
        }
        __syncwarp();
#pragma unroll
        for (int i = 0; i < 8; i++) {
            float a, c;
            unpack2(tp[i], a, c);
            W2p[(2 * i) * 20 + col] = a + c;
            W2p[(2 * i + 1) * 20 + col] = a - c;
        }
        __syncwarp();
        ull up[8];
#pragma unroll
        for (int j = 0; j < 4; j++) {
            float4 v = *(const float4*)(W2p + col * 20 + 4 * j);
            up[2 * j] = pack2(v.x, v.y);
            up[2 * j + 1] = pack2(v.z, v.w);
        }
#pragma unroll
        for (int mm = 1; mm < 8; mm <<= 1) {
#pragma unroll
            for (int i = 0; i < 8; i++)
                if (!(i & mm)) {
                    ull lo = up[i], hi = up[i | mm];
                    up[i] = fma2(hi, ONE2, lo);
                    up[i | mm] = fma2(hi, NEG2, lo);
                }
        }
        float bf = __ldg(bias2 + f);
        float pv[8];
#pragma unroll
        for (int k = 0; k < 8; k++) {
            float A, B;
            unpack2(up[k], A, B);
            float t = A + fabsf(B);
            float o = __shfl_xor_sync(~0u, t, 1);
            float pm = fmaxf(t, o);
            pv[k] = fmaxf(pm + bf, 0.f);
        }
        if (!(lane & 1)) {
            uint4 q;
            __half2 h0 = __floats2half2_rn(pv[0], pv[1]);
            __half2 h1 = __floats2half2_rn(pv[2], pv[3]);
            __half2 h2 = __floats2half2_rn(pv[4], pv[5]);
            __half2 h3 = __floats2half2_rn(pv[6], pv[7]);
            q.x = *(uint32_t*)&h0; q.y = *(uint32_t*)&h1;
            q.z = *(uint32_t*)&h2; q.w = *(uint32_t*)&h3;
            *(uint4*)(g_a + (size_t)(b0 + hw) * 4096 + f * 64 + (col >> 1) * 8) = q;
        }
    }
}

// ---------------- K3: FC1 GEMM (warp 32x64, K-chunk 128, K-split 2, 3-stage) --
#define STG3 65536
#define NCH3 16

__global__ void __launch_bounds__(256) k3_fc1() {
    extern __shared__ char smem[];
    uint32_t sb = smem_u32(smem);
    int tid = threadIdx.x, wid = tid >> 5, lane = tid & 31;
    int mt = blockIdx.x, nt = blockIdx.y, ks = blockIdx.z;
    int wm = wid & 3, wn = wid >> 2;

    float acc[2][8][4];
#pragma unroll
    for (int a = 0; a < 2; a++)
#pragma unroll
        for (int b = 0; b < 8; b++)
#pragma unroll
            for (int c = 0; c < 4; c++) acc[a][b][c] = 0.f;

    auto load_chunk = [&](int c, int s) {
        uint32_t st = sb + s * STG3;
        int kc = ks * 2048 + c * 128;
        const char* asrc = (const char*)(g_a + (size_t)mt * 128 * 4096 + kc);
#pragma unroll
        for (int j = 0; j < 8; j++) {
            int u = tid + j * 256, row = u >> 4, ck = u & 15;
            cpasync16(st + swz256(row, ck), asrc + (size_t)row * 8192 + ck * 16);
        }
        const char* bsrc = (const char*)(g_w + (size_t)nt * 128 * 4096 + kc);
#pragma unroll
        for (int j = 0; j < 8; j++) {
            int u = tid + j * 256, row = u >> 4, ck = u & 15;
            cpasync16(st + 32768 + swz256(row, ck), bsrc + (size_t)row * 8192 + ck * 16);
        }
        cp_commit();
    };

    auto load_regs = [&](uint32_t st, int kq, uint32_t ah[2][4], uint32_t bh[4][4]) {
#pragma unroll
        for (int tm = 0; tm < 2; tm++) {
            int row = wm * 32 + tm * 16 + (lane & 15);
            int ck = kq * 2 + (lane >> 4);
            ldsm_x4(st + swz256(row, ck), ah[tm]);
        }
#pragma unroll
        for (int tn = 0; tn < 4; tn++) {
            int n = wn * 64 + tn * 16 + (lane & 7) + ((lane >> 4) << 3);
            int ck = kq * 2 + ((lane >> 3) & 1);
            ldsm_x4(st + 32768 + swz256(n, ck), bh[tn]);
        }
    };

    load_chunk(0, 0);
    load_chunk(1, 1);

    int s = 0, s2 = 2;
    for (int i = 0; i < NCH3; i++) {
        if (i + 1 < NCH3) {
            asm volatile("cp.async.wait_group 1;" ::: "memory");
        } else {
            asm volatile("cp.async.wait_group 0;" ::: "memory");
        }
        __syncthreads();
        if (i + 2 < NCH3) load_chunk(i + 2, s2);

        uint32_t st = sb + s * STG3;
        uint32_t ah[2][2][4], bh[2][4][4];
        load_regs(st, 0, ah[0], bh[0]);
#pragma unroll
        for (int kq = 0; kq < 8; kq++) {
            int cur = kq & 1;
            if (kq < 7) load_regs(st, kq + 1, ah[cur ^ 1], bh[cur ^ 1]);
#pragma unroll
            for (int tm = 0; tm < 2; tm++)
#pragma unroll
                for (int j = 0; j < 8; j++)
                    mma_f16(acc[tm][j], ah[cur][tm], &bh[cur][j >> 1][(j & 1) * 2]);
        }
        s = (s == 2) ? 0 : s + 1;
        s2 = (s2 == 2) ? 0 : s2 + 1;
    }

    int g = lane >> 2, t = lane & 3;
    float* hb = g_h + (size_t)ks * 2048 * 512;
#pragma unroll
    for (int tm = 0; tm < 2; tm++)
#pragma unroll
        for (int j = 0; j < 8; j++) {
            int row0 = mt * 128 + wm * 32 + tm * 16 + g;
            int col = nt * 128 + wn * 64 + j * 8 + 2 * t;
            float* o0 = hb + (size_t)row0 * 512 + col;
            o0[0] = acc[tm][j][0];
            o0[1] = acc[tm][j][1];
            float* o1 = hb + (size_t)(row0 + 8) * 512 + col;
            o1[0] = acc[tm][j][2];
            o1[1] = acc[tm][j][3];
        }
}

// ---------------- K4: FC2 + softmax (MLP-restructured) ------------------------
__global__ void __launch_bounds__(256) k4_fc2(const float* __restrict__ fc1b,
                                              const float* __restrict__ w,
                                              const float* __restrict__ fc2b,
                                              float* __restrict__ out) {
    int warp = (blockIdx.x * blockDim.x + threadIdx.x) >> 5;
    int lane = threadIdx.x & 31;
    const float4* h0 = (const float4*)(g_h + (size_t)warp * 512 + lane * 16);
    const float4* h1 = (const float4*)(g_h + 2048 * 512 + (size_t)warp * 512 + lane * 16);
    const float4* b4 = (const float4*)(fc1b + lane * 16);
    float4 xv[4];
#pragma unroll
    for (int j = 0; j < 4; j++) {
        float4 a = h0[j], b = h1[j], c = __ldg(b4 + j);
        xv[j].x = fmaxf(a.x + b.x + c.x, 0.f);
        xv[j].y = fmaxf(a.y + b.y + c.y, 0.f);
        xv[j].z = fmaxf(a.z + b.z + c.z, 0.f);
        xv[j].w = fmaxf(a.w + b.w + c.w, 0.f);
    }
    float l[10];
#pragma unroll
    for (int o = 0; o < 10; o++) l[o] = 0.f;
#pragma unroll
    for (int j = 0; j < 4; j++) {
#pragma unroll
        for (int o = 0; o < 10; o++) {
            float4 wv = __ldg((const float4*)(w + o * 512 + lane * 16) + j);
            l[o] += xv[j].x * wv.x + xv[j].y * wv.y + xv[j].z * wv.z + xv[j].w * wv.w;
        }
    }
#pragma unroll
    for (int m = 16; m >= 1; m >>= 1)
#pragma unroll
        for (int o = 0; o < 10; o++) l[o] += __shfl_xor_sync(~0u, l[o], m);
#pragma unroll
    for (int o = 0; o < 10; o++) l[o] += __ldg(fc2b + o);

    float mx = l[0];
#pragma unroll
    for (int o = 1; o < 10; o++) mx = fmaxf(mx, l[o]);
    float s = 0.f;
#pragma unroll
    for (int o = 0; o < 10; o++) { l[o] = __expf(l[o] - mx); s += l[o]; }
    float inv = 1.f / s;
    if (lane < 10) out[(size_t)warp * 10 + lane] = l[lane] * inv;
}

// ---------------- launch ------------------------------------------------------
extern "C" void kernel_launch(void* const* d_in, const int* in_sizes, int n_in,
                              void* d_out, int out_size) {
    const float* x    = (const float*)d_in[0];
    const float* f1   = (const float*)d_in[1];
    const float* b1   = (const float*)d_in[2];
    const float* f2   = (const float*)d_in[3];
    const float* b2   = (const float*)d_in[4];
    const float* fc1w = (const float*)d_in[5];
    const float* fc1b = (const float*)d_in[6];
    const float* fc2w = (const float*)d_in[7];
    const float* fc2b = (const float*)d_in[8];
    float* out = (float*)d_out;

    const int smem3 = 3 * STG3;  // 196608 bytes
    cudaFuncSetAttribute(k3_fc1, cudaFuncAttributeMaxDynamicSharedMemorySize, smem3);

    // main stream: filter transforms, then conv layers
    kf_filters<<<192, 256>>>(f1, f2);

    // fork: weight conversion runs concurrently on the side stream
    cudaEventRecord(g_si.evFork, 0);
    cudaStreamWaitEvent(g_si.s, g_si.evFork, 0);
    kw_conv<<<2048, 256, 0, g_si.s>>>(fc1w);
    cudaEventRecord(g_si.evJoin, g_si.s);

    k1_layer1<<<2048, 256>>>(x, b1);
    k2_layer2<<<1024, 256>>>(b2);

    // join: k3 needs both g_a (main) and g_w (side)
    cudaStreamWaitEvent(0, g_si.evJoin, 0);
    k3_fc1<<<dim3(16, 4, 2), 256, smem3>>>();
    k4_fc2<<<256, 256>>>(fc1b, fc2w, fc2b, out);
}